// round 2
// baseline (speedup 1.0000x reference)
#include <cuda_runtime.h>
#include <cuda_bf16.h>

// Problem constants (fixed by the reference setup)
#define NN 100000
#define HH 64
#define GG 512

// -------- scratch (device globals; no allocation allowed) --------
__device__ float g_deg[NN];          // in-degree (float)
__device__ float g_dinv[NN];         // rsqrt(deg+1)
__device__ float g_t[NN * HH];       // transformed features h = x @ W
__device__ float g_agg[NN * HH];     // neighbor aggregation
__device__ float g_f[NN * HH];       // layer output (relu)
__device__ float g_pool[GG * HH];    // per-graph sums
__device__ float g_cnt[GG];          // per-graph node counts

// -------- helpers --------
__device__ __forceinline__ void red_add_v4(float* p, float4 v) {
    asm volatile(
        "{ .reg .u64 a; cvta.to.global.u64 a, %0;"
        "  red.global.add.v4.f32 [a], {%1, %2, %3, %4}; }"
        :: "l"(p), "f"(v.x), "f"(v.y), "f"(v.z), "f"(v.w)
        : "memory");
}

__global__ void k_zero(float* p, int n) {
    int i = blockIdx.x * blockDim.x + threadIdx.x;
    int stride = gridDim.x * blockDim.x;
    for (; i < n; i += stride) p[i] = 0.0f;
}

__global__ void k_deg(const int* __restrict__ dst, int E) {
    int e = blockIdx.x * blockDim.x + threadIdx.x;
    if (e < E) atomicAdd(&g_deg[dst[e]], 1.0f);
}

__global__ void k_dinv(int n) {
    int i = blockIdx.x * blockDim.x + threadIdx.x;
    if (i < n) g_dinv[i] = rsqrtf(g_deg[i] + 1.0f);
}

// h = x @ W1   (x: [N,2], W1: [2,64] row-major)
__global__ void k_xform1(const float* __restrict__ x, const float* __restrict__ W1, int n) {
    int idx = blockIdx.x * blockDim.x + threadIdx.x;
    if (idx >= n * HH) return;
    int i = idx >> 6;
    int j = idx & 63;
    g_t[idx] = x[2 * i] * W1[j] + x[2 * i + 1] * W1[HH + j];
}

// Edge scatter: agg[dst] += g_t[src] * dinv[src]*dinv[dst]
// One thread per (edge, 16B chunk): E*16 threads, float4 loads + v4 reductions.
__global__ void k_scatter(const int* __restrict__ src, const int* __restrict__ dst, int E) {
    long long idx = (long long)blockIdx.x * blockDim.x + threadIdx.x;
    if (idx >= (long long)E * 16) return;
    int e = (int)(idx >> 4);
    int c = (int)(idx & 15);
    int s = src[e];
    int d = dst[e];
    float norm = g_dinv[s] * g_dinv[d];
    float4 v = *reinterpret_cast<const float4*>(&g_t[(long long)s * HH + c * 4]);
    v.x *= norm; v.y *= norm; v.z *= norm; v.w *= norm;
    red_add_v4(&g_agg[(long long)d * HH + c * 4], v);
}

// out = relu(agg + t * dinv^2 + b)
__global__ void k_combine(const float* __restrict__ b, float* __restrict__ out, int n) {
    int idx = blockIdx.x * blockDim.x + threadIdx.x;
    if (idx >= n * HH) return;
    int i = idx >> 6;
    int j = idx & 63;
    float dv = g_dinv[i];
    float v = g_agg[idx] + g_t[idx] * dv * dv + b[j];
    out[idx] = fmaxf(v, 0.0f);
}

// t = f @ W2   (per-node 64-vec x 64x64 matrix). 4 nodes per 256-thread block.
__global__ void k_xform2(const float* __restrict__ fin, const float* __restrict__ W2, int n) {
    __shared__ float sW[HH * HH];
    __shared__ float sRow[4 * HH];
    int tid = threadIdx.x;
    int grp = tid >> 6;        // node within block (0..3)
    int j = tid & 63;          // output feature
    int node = blockIdx.x * 4 + grp;

    #pragma unroll
    for (int i = tid; i < HH * HH; i += 256) sW[i] = W2[i];
    if (node < n) sRow[grp * HH + j] = fin[(long long)node * HH + j];
    __syncthreads();

    if (node >= n) return;
    float acc = 0.0f;
    #pragma unroll
    for (int k = 0; k < HH; k++) acc += sRow[grp * HH + k] * sW[k * HH + j];
    g_t[(long long)node * HH + j] = acc;
}

__global__ void k_cnt(const int* __restrict__ batch, int n) {
    int i = blockIdx.x * blockDim.x + threadIdx.x;
    if (i < n) atomicAdd(&g_cnt[batch[i]], 1.0f);
}

// pool[batch[i]] += f[i]  (v4 reductions)
__global__ void k_pool(const int* __restrict__ batch, int n) {
    int idx = blockIdx.x * blockDim.x + threadIdx.x;
    if (idx >= n * 16) return;
    int i = idx >> 4;
    int c = idx & 15;
    int b = batch[i];
    float4 v = *reinterpret_cast<const float4*>(&g_f[(long long)i * HH + c * 4]);
    red_add_v4(&g_pool[(long long)b * HH + c * 4], v);
}

// Final head: g = pool/cnt; a = relu(g@Wf1+bf1); out = a@Wf2+bf2
__global__ void k_final(const float* __restrict__ Wf1, const float* __restrict__ bf1,
                        const float* __restrict__ Wf2, const float* __restrict__ bf2,
                        float* __restrict__ out) {
    __shared__ float sg[HH];
    __shared__ float sa[HH];
    int b = blockIdx.x;
    int j = threadIdx.x;

    float c = fmaxf(g_cnt[b], 1.0f);
    sg[j] = g_pool[b * HH + j] / c;
    __syncthreads();

    float acc = bf1[j];
    #pragma unroll
    for (int k = 0; k < HH; k++) acc += sg[k] * Wf1[k * HH + j];
    sa[j] = fmaxf(acc, 0.0f);
    __syncthreads();

    if (j < 4) {
        float o = bf2[j];
        #pragma unroll
        for (int k = 0; k < HH; k++) o += sa[k] * Wf2[k * 4 + j];
        out[b * 4 + j] = o;
    }
}

extern "C" void kernel_launch(void* const* d_in, const int* in_sizes, int n_in,
                              void* d_out, int out_size) {
    const float* x          = (const float*)d_in[0];
    const int*   edge_index = (const int*)d_in[1];
    const int*   batch      = (const int*)d_in[2];
    // weights always the last 8 inputs (num_graphs scalar may or may not be present)
    int wb = n_in - 8;
    const float* W1  = (const float*)d_in[wb + 0];
    const float* b1  = (const float*)d_in[wb + 1];
    const float* W2  = (const float*)d_in[wb + 2];
    const float* b2  = (const float*)d_in[wb + 3];
    const float* Wf1 = (const float*)d_in[wb + 4];
    const float* bf1 = (const float*)d_in[wb + 5];
    const float* Wf2 = (const float*)d_in[wb + 6];
    const float* bf2 = (const float*)d_in[wb + 7];

    int N = in_sizes[0] / 2;       // 100000
    int E = in_sizes[1] / 2;       // 1200000
    const int* src = edge_index;
    const int* dst = edge_index + E;

    float* out = (float*)d_out;
    (void)out_size;

    float* p_deg;  cudaGetSymbolAddress((void**)&p_deg,  g_deg);
    float* p_agg;  cudaGetSymbolAddress((void**)&p_agg,  g_agg);
    float* p_pool; cudaGetSymbolAddress((void**)&p_pool, g_pool);
    float* p_cnt;  cudaGetSymbolAddress((void**)&p_cnt,  g_cnt);
    float* p_f;    cudaGetSymbolAddress((void**)&p_f,    g_f);

    const int T = 256;
    int gN   = (N + T - 1) / T;
    int gNH  = (N * HH + T - 1) / T;
    int gE   = (E + T - 1) / T;
    long long e16 = (long long)E * 16;
    int gE16 = (int)((e16 + T - 1) / T);
    int gN16 = (N * 16 + T - 1) / T;

    // init
    k_zero<<<gN, T>>>(p_deg, N);
    k_zero<<<gNH, T>>>(p_agg, N * HH);
    k_zero<<<(GG * HH + T - 1) / T, T>>>(p_pool, GG * HH);
    k_zero<<<(GG + T - 1) / T, T>>>(p_cnt, GG);

    // degree + norm
    k_deg<<<gE, T>>>(dst, E);
    k_dinv<<<gN, T>>>(N);

    // ---- layer 1 ----
    k_xform1<<<gNH, T>>>(x, W1, N);
    k_scatter<<<gE16, T>>>(src, dst, E);
    k_combine<<<gNH, T>>>(b1, p_f, N);

    // ---- layer 2 ----
    k_zero<<<gNH, T>>>(p_agg, N * HH);
    k_xform2<<<(N + 3) / 4, 256>>>(p_f, W2, N);
    k_scatter<<<gE16, T>>>(src, dst, E);
    k_combine<<<gNH, T>>>(b2, p_f, N);

    // ---- pool + head ----
    k_cnt<<<gN, T>>>(batch, N);
    k_pool<<<gN16, T>>>(batch, N);
    k_final<<<GG, HH>>>(Wf1, bf1, Wf2, bf2, out);
}

// round 3
// speedup vs baseline: 1.2817x; 1.2817x over previous
#include <cuda_runtime.h>
#include <cuda_bf16.h>

#define NN 100000
#define EE_MAX 1300000
#define HH 64
#define GG 512
#define SCAN_B 256
#define NBLK ((NN + SCAN_B - 1) / SCAN_B)   // 391

// -------- scratch (device globals) --------
__device__ int   g_ideg[NN];         // in-degree (int)
__device__ int   g_off[NN];          // CSR row offsets (exclusive scan of ideg)
__device__ int   g_cur[NN];          // fill cursors
__device__ int   g_bsum[NBLK];       // scan block sums
__device__ int   g_csrc[EE_MAX];     // CSR: src node per incoming edge, grouped by dst
__device__ float g_dinv[NN];         // rsqrt(deg+1)
__device__ float g_t[NN * HH];       // pre-scaled transformed features t' = dinv * (h @ W)
__device__ float g_f[NN * HH];       // layer-1 output
__device__ float g_pool[GG * HH];    // per-graph sums
__device__ float g_cnt[GG];          // per-graph node counts

__global__ void k_zero_f(float* p, int n) {
    int i = blockIdx.x * blockDim.x + threadIdx.x;
    if (i < n) p[i] = 0.0f;
}
__global__ void k_zero_i(int* p, int n) {
    int i = blockIdx.x * blockDim.x + threadIdx.x;
    if (i < n) p[i] = 0;
}

__global__ void k_hist(const int* __restrict__ dst, int E) {
    int e = blockIdx.x * blockDim.x + threadIdx.x;
    if (e < E) atomicAdd(&g_ideg[dst[e]], 1);
}

// --- 2-level exclusive scan of g_ideg -> g_off ---
__global__ void k_scan1() {
    __shared__ int s[SCAN_B];
    int i = blockIdx.x * SCAN_B + threadIdx.x;
    int v = (i < NN) ? g_ideg[i] : 0;
    s[threadIdx.x] = v;
    __syncthreads();
    for (int o = 1; o < SCAN_B; o <<= 1) {
        int t = (threadIdx.x >= o) ? s[threadIdx.x - o] : 0;
        __syncthreads();
        s[threadIdx.x] += t;
        __syncthreads();
    }
    if (i < NN) g_off[i] = s[threadIdx.x] - v;       // exclusive within block
    if (threadIdx.x == SCAN_B - 1) g_bsum[blockIdx.x] = s[SCAN_B - 1];
}

__global__ void k_scan2() {   // single block of 512, NBLK=391 fits
    __shared__ int s[512];
    int tid = threadIdx.x;
    int v = (tid < NBLK) ? g_bsum[tid] : 0;
    s[tid] = v;
    __syncthreads();
    for (int o = 1; o < 512; o <<= 1) {
        int t = (tid >= o) ? s[tid - o] : 0;
        __syncthreads();
        s[tid] += t;
        __syncthreads();
    }
    if (tid < NBLK) g_bsum[tid] = s[tid] - v;        // exclusive
}

__global__ void k_scan3() {
    int i = blockIdx.x * blockDim.x + threadIdx.x;
    if (i < NN) {
        int o = g_off[i] + g_bsum[i >> 8];
        g_off[i] = o;
        g_cur[i] = o;
        g_dinv[i] = rsqrtf((float)g_ideg[i] + 1.0f);
    }
}

__global__ void k_fill(const int* __restrict__ src, const int* __restrict__ dst, int E) {
    int e = blockIdx.x * blockDim.x + threadIdx.x;
    if (e < E) {
        int d = dst[e];
        int p = atomicAdd(&g_cur[d], 1);
        g_csrc[p] = src[e];
    }
}

// t1' = dinv[i] * (x[i] @ W1)   (x: [N,2], W1: [2,64])
__global__ void k_xform1(const float* __restrict__ x, const float* __restrict__ W1, int n) {
    int idx = blockIdx.x * blockDim.x + threadIdx.x;
    if (idx >= n * HH) return;
    int i = idx >> 6;
    int j = idx & 63;
    g_t[idx] = g_dinv[i] * (x[2 * i] * W1[j] + x[2 * i + 1] * W1[HH + j]);
}

// f1 = relu(dinv[d] * (self + sum of t'[src]) + b1)
__global__ void k_agg1(const float* __restrict__ b1) {
    int d = blockIdx.x;
    int j = threadIdx.x;
    int beg = g_off[d];
    int len = g_ideg[d];
    float acc = g_t[d * HH + j];   // self term
    int k = 0;
    for (; k + 4 <= len; k += 4) {
        int s0 = g_csrc[beg + k + 0];
        int s1 = g_csrc[beg + k + 1];
        int s2 = g_csrc[beg + k + 2];
        int s3 = g_csrc[beg + k + 3];
        float a0 = g_t[s0 * HH + j];
        float a1 = g_t[s1 * HH + j];
        float a2 = g_t[s2 * HH + j];
        float a3 = g_t[s3 * HH + j];
        acc += (a0 + a1) + (a2 + a3);
    }
    for (; k < len; k++) acc += g_t[g_csrc[beg + k] * HH + j];
    g_f[d * HH + j] = fmaxf(g_dinv[d] * acc + b1[j], 0.0f);
}

// t2' = dinv[i] * (f1[i] @ W2); 4 nodes per 256-thread block, W2 in smem
__global__ void k_xform2(const float* __restrict__ W2, int n) {
    __shared__ float sW[HH * HH];
    __shared__ float sRow[4 * HH];
    int tid = threadIdx.x;
    int grp = tid >> 6;
    int j = tid & 63;
    int node = blockIdx.x * 4 + grp;

    for (int i = tid; i < HH * HH; i += 256) sW[i] = W2[i];
    if (node < n) sRow[grp * HH + j] = g_f[node * HH + j];
    __syncthreads();

    if (node >= n) return;
    float acc = 0.0f;
    #pragma unroll
    for (int kk = 0; kk < HH; kk++) acc += sRow[grp * HH + kk] * sW[kk * HH + j];
    g_t[node * HH + j] = g_dinv[node] * acc;
}

// layer-2 agg fused with pooling: val = relu(dinv*(...)+b2); pool[batch[d]] += val
__global__ void k_agg2pool(const float* __restrict__ b2, const int* __restrict__ batch) {
    int d = blockIdx.x;
    int j = threadIdx.x;
    int beg = g_off[d];
    int len = g_ideg[d];
    float acc = g_t[d * HH + j];
    int k = 0;
    for (; k + 4 <= len; k += 4) {
        int s0 = g_csrc[beg + k + 0];
        int s1 = g_csrc[beg + k + 1];
        int s2 = g_csrc[beg + k + 2];
        int s3 = g_csrc[beg + k + 3];
        float a0 = g_t[s0 * HH + j];
        float a1 = g_t[s1 * HH + j];
        float a2 = g_t[s2 * HH + j];
        float a3 = g_t[s3 * HH + j];
        acc += (a0 + a1) + (a2 + a3);
    }
    for (; k < len; k++) acc += g_t[g_csrc[beg + k] * HH + j];
    float val = fmaxf(g_dinv[d] * acc + b2[j], 0.0f);
    atomicAdd(&g_pool[batch[d] * HH + j], val);
}

__global__ void k_cnt(const int* __restrict__ batch, int n) {
    int i = blockIdx.x * blockDim.x + threadIdx.x;
    if (i < n) atomicAdd(&g_cnt[batch[i]], 1.0f);
}

// Head: g = pool/cnt; a = relu(g@Wf1+bf1); out = a@Wf2+bf2
__global__ void k_final(const float* __restrict__ Wf1, const float* __restrict__ bf1,
                        const float* __restrict__ Wf2, const float* __restrict__ bf2,
                        float* __restrict__ out) {
    __shared__ float sg[HH];
    __shared__ float sa[HH];
    int b = blockIdx.x;
    int j = threadIdx.x;

    float c = fmaxf(g_cnt[b], 1.0f);
    sg[j] = g_pool[b * HH + j] / c;
    __syncthreads();

    float acc = bf1[j];
    #pragma unroll
    for (int k = 0; k < HH; k++) acc += sg[k] * Wf1[k * HH + j];
    sa[j] = fmaxf(acc, 0.0f);
    __syncthreads();

    if (j < 4) {
        float o = bf2[j];
        #pragma unroll
        for (int k = 0; k < HH; k++) o += sa[k] * Wf2[k * 4 + j];
        out[b * 4 + j] = o;
    }
}

extern "C" void kernel_launch(void* const* d_in, const int* in_sizes, int n_in,
                              void* d_out, int out_size) {
    const float* x          = (const float*)d_in[0];
    const int*   edge_index = (const int*)d_in[1];
    const int*   batch      = (const int*)d_in[2];
    int wb = n_in - 8;
    const float* W1  = (const float*)d_in[wb + 0];
    const float* b1  = (const float*)d_in[wb + 1];
    const float* W2  = (const float*)d_in[wb + 2];
    const float* b2  = (const float*)d_in[wb + 3];
    const float* Wf1 = (const float*)d_in[wb + 4];
    const float* bf1 = (const float*)d_in[wb + 5];
    const float* Wf2 = (const float*)d_in[wb + 6];
    const float* bf2 = (const float*)d_in[wb + 7];

    int N = in_sizes[0] / 2;   // 100000
    int E = in_sizes[1] / 2;   // 1200000
    const int* src = edge_index;
    const int* dst = edge_index + E;

    float* out = (float*)d_out;
    (void)out_size;

    int*   p_ideg; cudaGetSymbolAddress((void**)&p_ideg, g_ideg);
    float* p_pool; cudaGetSymbolAddress((void**)&p_pool, g_pool);
    float* p_cnt;  cudaGetSymbolAddress((void**)&p_cnt,  g_cnt);

    const int T = 256;
    int gN  = (N + T - 1) / T;
    int gNH = (N * HH + T - 1) / T;
    int gE  = (E + T - 1) / T;

    // ---- CSR build + norms ----
    k_zero_i<<<gN, T>>>(p_ideg, N);
    k_zero_f<<<(GG * HH + T - 1) / T, T>>>(p_pool, GG * HH);
    k_zero_f<<<(GG + T - 1) / T, T>>>(p_cnt, GG);
    k_hist<<<gE, T>>>(dst, E);
    k_scan1<<<NBLK, SCAN_B>>>();
    k_scan2<<<1, 512>>>();
    k_scan3<<<gN, T>>>();
    k_fill<<<gE, T>>>(src, dst, E);

    // ---- layer 1 ----
    k_xform1<<<gNH, T>>>(x, W1, N);
    k_agg1<<<N, HH>>>(b1);

    // ---- layer 2 (agg fused with pool) ----
    k_xform2<<<(N + 3) / 4, 256>>>(W2, N);
    k_cnt<<<gN, T>>>(batch, N);
    k_agg2pool<<<N, HH>>>(b2, batch);

    // ---- head ----
    k_final<<<GG, HH>>>(Wf1, bf1, Wf2, bf2, out);
}

// round 4
// speedup vs baseline: 1.3757x; 1.0733x over previous
#include <cuda_runtime.h>
#include <cuda_bf16.h>

#define NN 100000
#define EE_MAX 1300000
#define HH 64
#define GG 512
#define SCAN_B 256
#define NBLK ((NN + SCAN_B - 1) / SCAN_B)   // 391

// -------- scratch (device globals) --------
__device__ int   g_ideg[NN];         // in-degree
__device__ int   g_off[NN];          // CSR row offsets
__device__ int   g_cur[NN];          // fill cursors
__device__ int   g_bsum[NBLK];       // scan block sums
__device__ int   g_csrc[EE_MAX];     // CSR src lists grouped by dst
__device__ float g_dinv[NN];         // rsqrt(deg+1)
__device__ float g_t[NN * HH];       // pre-scaled transformed features t' = dinv * (h @ W)
__device__ float g_f[NN * HH];       // layer-1 output
__device__ float g_pool[GG * HH];    // per-graph sums
__device__ float g_cnt[GG];          // per-graph node counts

// zero everything that needs zeroing in one launch
__global__ void k_zero_all() {
    int i = blockIdx.x * blockDim.x + threadIdx.x;
    if (i < NN) g_ideg[i] = 0;
    if (i < GG * HH) g_pool[i] = 0.0f;
    if (i < GG) g_cnt[i] = 0.0f;
}

__global__ void k_hist(const int* __restrict__ dst, int E) {
    int e = blockIdx.x * blockDim.x + threadIdx.x;
    if (e < E) atomicAdd(&g_ideg[dst[e]], 1);
}

// --- 2-level exclusive scan of g_ideg -> g_off ---
__global__ void k_scan1() {
    __shared__ int s[SCAN_B];
    int i = blockIdx.x * SCAN_B + threadIdx.x;
    int v = (i < NN) ? g_ideg[i] : 0;
    s[threadIdx.x] = v;
    __syncthreads();
    for (int o = 1; o < SCAN_B; o <<= 1) {
        int t = (threadIdx.x >= o) ? s[threadIdx.x - o] : 0;
        __syncthreads();
        s[threadIdx.x] += t;
        __syncthreads();
    }
    if (i < NN) g_off[i] = s[threadIdx.x] - v;
    if (threadIdx.x == SCAN_B - 1) g_bsum[blockIdx.x] = s[SCAN_B - 1];
}

__global__ void k_scan2() {   // one block of 512 covers NBLK=391
    __shared__ int s[512];
    int tid = threadIdx.x;
    int v = (tid < NBLK) ? g_bsum[tid] : 0;
    s[tid] = v;
    __syncthreads();
    for (int o = 1; o < 512; o <<= 1) {
        int t = (tid >= o) ? s[tid - o] : 0;
        __syncthreads();
        s[tid] += t;
        __syncthreads();
    }
    if (tid < NBLK) g_bsum[tid] = s[tid] - v;
}

// finalize offsets + dinv, and fold in the per-graph node counts
__global__ void k_scan3(const int* __restrict__ batch, int n) {
    int i = blockIdx.x * blockDim.x + threadIdx.x;
    if (i < n) {
        int o = g_off[i] + g_bsum[i >> 8];
        g_off[i] = o;
        g_cur[i] = o;
        g_dinv[i] = rsqrtf((float)g_ideg[i] + 1.0f);
        atomicAdd(&g_cnt[batch[i]], 1.0f);
    }
}

__global__ void k_fill(const int* __restrict__ src, const int* __restrict__ dst, int E) {
    int e = blockIdx.x * blockDim.x + threadIdx.x;
    if (e < E) {
        int d = dst[e];
        int p = atomicAdd(&g_cur[d], 1);
        g_csrc[p] = src[e];
    }
}

// t1' = dinv[i] * (x[i] @ W1)
__global__ void k_xform1(const float* __restrict__ x, const float* __restrict__ W1, int n) {
    int idx = blockIdx.x * blockDim.x + threadIdx.x;
    if (idx >= n * HH) return;
    int i = idx >> 6;
    int j = idx & 63;
    g_t[idx] = g_dinv[i] * (x[2 * i] * W1[j] + x[2 * i + 1] * W1[HH + j]);
}

// warp-per-node aggregation: f1 = relu(dinv[d]*(self + sum t'[src]) + b1)
__global__ void k_agg1(const float* __restrict__ b1, int n) {
    int w = (blockIdx.x * blockDim.x + threadIdx.x) >> 5;   // node
    int lane = threadIdx.x & 31;
    if (w >= n) return;
    int beg = g_off[w];
    int len = g_ideg[w];
    float2 acc = *reinterpret_cast<const float2*>(&g_t[w * HH + lane * 2]);  // self
    for (int base = 0; base < len; base += 32) {
        int rem = len - base;
        int m = rem < 32 ? rem : 32;
        int idx = (lane < m) ? g_csrc[beg + base + lane] : 0;
        #pragma unroll 4
        for (int k = 0; k < m; k++) {
            int s = __shfl_sync(0xffffffffu, idx, k);
            float2 v = *reinterpret_cast<const float2*>(&g_t[s * HH + lane * 2]);
            acc.x += v.x;
            acc.y += v.y;
        }
    }
    float dv = g_dinv[w];
    float2 bb = *reinterpret_cast<const float2*>(&b1[lane * 2]);
    float2 o;
    o.x = fmaxf(fmaf(dv, acc.x, bb.x), 0.0f);
    o.y = fmaxf(fmaf(dv, acc.y, bb.y), 0.0f);
    *reinterpret_cast<float2*>(&g_f[w * HH + lane * 2]) = o;
}

// t2' = dinv[i] * (f1[i] @ W2); 4 nodes per 256-thread block, W2 in smem
__global__ void k_xform2(const float* __restrict__ W2, int n) {
    __shared__ float sW[HH * HH];
    __shared__ float sRow[4 * HH];
    int tid = threadIdx.x;
    int grp = tid >> 6;
    int j = tid & 63;
    int node = blockIdx.x * 4 + grp;

    for (int i = tid; i < HH * HH; i += 256) sW[i] = W2[i];
    if (node < n) sRow[grp * HH + j] = g_f[node * HH + j];
    __syncthreads();

    if (node >= n) return;
    float acc = 0.0f;
    #pragma unroll
    for (int kk = 0; kk < HH; kk++) acc += sRow[grp * HH + kk] * sW[kk * HH + j];
    g_t[node * HH + j] = g_dinv[node] * acc;
}

// warp-per-node layer-2 agg fused with pooling
__global__ void k_agg2pool(const float* __restrict__ b2, const int* __restrict__ batch, int n) {
    int w = (blockIdx.x * blockDim.x + threadIdx.x) >> 5;
    int lane = threadIdx.x & 31;
    if (w >= n) return;
    int beg = g_off[w];
    int len = g_ideg[w];
    float2 acc = *reinterpret_cast<const float2*>(&g_t[w * HH + lane * 2]);
    for (int base = 0; base < len; base += 32) {
        int rem = len - base;
        int m = rem < 32 ? rem : 32;
        int idx = (lane < m) ? g_csrc[beg + base + lane] : 0;
        #pragma unroll 4
        for (int k = 0; k < m; k++) {
            int s = __shfl_sync(0xffffffffu, idx, k);
            float2 v = *reinterpret_cast<const float2*>(&g_t[s * HH + lane * 2]);
            acc.x += v.x;
            acc.y += v.y;
        }
    }
    float dv = g_dinv[w];
    float2 bb = *reinterpret_cast<const float2*>(&b2[lane * 2]);
    float vx = fmaxf(fmaf(dv, acc.x, bb.x), 0.0f);
    float vy = fmaxf(fmaf(dv, acc.y, bb.y), 0.0f);
    int b = batch[w];
    atomicAdd(&g_pool[b * HH + lane * 2 + 0], vx);
    atomicAdd(&g_pool[b * HH + lane * 2 + 1], vy);
}

// Head: g = pool/cnt; a = relu(g@Wf1+bf1); out = a@Wf2+bf2
__global__ void k_final(const float* __restrict__ Wf1, const float* __restrict__ bf1,
                        const float* __restrict__ Wf2, const float* __restrict__ bf2,
                        float* __restrict__ out) {
    __shared__ float sg[HH];
    __shared__ float sa[HH];
    int b = blockIdx.x;
    int j = threadIdx.x;

    float c = fmaxf(g_cnt[b], 1.0f);
    sg[j] = g_pool[b * HH + j] / c;
    __syncthreads();

    float acc = bf1[j];
    #pragma unroll
    for (int k = 0; k < HH; k++) acc += sg[k] * Wf1[k * HH + j];
    sa[j] = fmaxf(acc, 0.0f);
    __syncthreads();

    if (j < 4) {
        float o = bf2[j];
        #pragma unroll
        for (int k = 0; k < HH; k++) o += sa[k] * Wf2[k * 4 + j];
        out[b * 4 + j] = o;
    }
}

extern "C" void kernel_launch(void* const* d_in, const int* in_sizes, int n_in,
                              void* d_out, int out_size) {
    const float* x          = (const float*)d_in[0];
    const int*   edge_index = (const int*)d_in[1];
    const int*   batch      = (const int*)d_in[2];
    int wb = n_in - 8;
    const float* W1  = (const float*)d_in[wb + 0];
    const float* b1  = (const float*)d_in[wb + 1];
    const float* W2  = (const float*)d_in[wb + 2];
    const float* b2  = (const float*)d_in[wb + 3];
    const float* Wf1 = (const float*)d_in[wb + 4];
    const float* bf1 = (const float*)d_in[wb + 5];
    const float* Wf2 = (const float*)d_in[wb + 6];
    const float* bf2 = (const float*)d_in[wb + 7];

    int N = in_sizes[0] / 2;   // 100000
    int E = in_sizes[1] / 2;   // 1200000
    const int* src = edge_index;
    const int* dst = edge_index + E;

    float* out = (float*)d_out;
    (void)out_size;

    const int T = 256;
    int gN  = (N + T - 1) / T;
    int gNH = (N * HH + T - 1) / T;
    int gE  = (E + T - 1) / T;
    int gW  = (N * 32 + T - 1) / T;   // warp-per-node grids (8 nodes / 256-thr block)

    // ---- CSR build + norms + counts ----
    k_zero_all<<<gN, T>>>();
    k_hist<<<gE, T>>>(dst, E);
    k_scan1<<<NBLK, SCAN_B>>>();
    k_scan2<<<1, 512>>>();
    k_scan3<<<gN, T>>>(batch, N);
    k_fill<<<gE, T>>>(src, dst, E);

    // ---- layer 1 ----
    k_xform1<<<gNH, T>>>(x, W1, N);
    k_agg1<<<gW, T>>>(b1, N);

    // ---- layer 2 (agg fused with pool) ----
    k_xform2<<<(N + 3) / 4, 256>>>(W2, N);
    k_agg2pool<<<gW, T>>>(b2, batch, N);

    // ---- head ----
    k_final<<<GG, HH>>>(Wf1, bf1, Wf2, bf2, out);
}

// round 6
// speedup vs baseline: 1.4286x; 1.0384x over previous
#include <cuda_runtime.h>
#include <cuda_fp16.h>

#define NN 100000
#define EE_MAX 1300000
#define HH 64
#define GG 512
#define SCAN_B 256
#define NBLK ((NN + SCAN_B - 1) / SCAN_B)   // 391

// -------- scratch (device globals) --------
__device__ int    g_ideg[NN];
__device__ int    g_off[NN];
__device__ int    g_cur[NN];
__device__ int    g_bsum[NBLK];
__device__ int    g_csrc[EE_MAX];
__device__ float  g_dinv[NN];
__device__ __half g_th[NN * HH];      // pre-scaled transformed features (fp16)
__device__ float  g_f[NN * HH];       // layer-1 output (fp32)
__device__ float  g_pool[GG * HH];
__device__ float  g_cnt[GG];

__global__ void k_zero_all() {
    int i = blockIdx.x * blockDim.x + threadIdx.x;
    if (i < NN) g_ideg[i] = 0;
    if (i < GG * HH) g_pool[i] = 0.0f;
    if (i < GG) g_cnt[i] = 0.0f;
}

__global__ void k_hist(const int* __restrict__ dst, int E) {
    int e = blockIdx.x * blockDim.x + threadIdx.x;
    if (e < E) atomicAdd(&g_ideg[dst[e]], 1);
}

// block-local inclusive scan -> exclusive offsets + per-block sums
__global__ void k_scan1() {
    __shared__ int s[SCAN_B];
    int i = blockIdx.x * SCAN_B + threadIdx.x;
    int v = (i < NN) ? g_ideg[i] : 0;
    s[threadIdx.x] = v;
    __syncthreads();
    for (int o = 1; o < SCAN_B; o <<= 1) {
        int t = (threadIdx.x >= o) ? s[threadIdx.x - o] : 0;
        __syncthreads();
        s[threadIdx.x] += t;
        __syncthreads();
    }
    if (i < NN) g_off[i] = s[threadIdx.x] - v;
    if (threadIdx.x == SCAN_B - 1) g_bsum[blockIdx.x] = s[SCAN_B - 1];
}

// fused: per-block prefix over g_bsum + finalize offsets/dinv/cursors + graph counts
__global__ void k_scan23(const int* __restrict__ batch, int n) {
    __shared__ int red[8];
    __shared__ int ssum;
    int tid = threadIdx.x;
    int partial = 0;
    for (int j = tid; j < (int)blockIdx.x; j += SCAN_B) partial += g_bsum[j];
    #pragma unroll
    for (int o = 16; o; o >>= 1) partial += __shfl_down_sync(0xffffffffu, partial, o);
    if ((tid & 31) == 0) red[tid >> 5] = partial;
    __syncthreads();
    if (tid == 0) {
        int s = 0;
        #pragma unroll
        for (int k = 0; k < 8; k++) s += red[k];
        ssum = s;
    }
    __syncthreads();
    int i = blockIdx.x * SCAN_B + tid;
    if (i < n) {
        int o = g_off[i] + ssum;
        g_off[i] = o;
        g_cur[i] = o;
        g_dinv[i] = rsqrtf((float)g_ideg[i] + 1.0f);
        atomicAdd(&g_cnt[batch[i]], 1.0f);
    }
}

// fused: CSR fill (first E threads) + layer-1 transform t1' = dinv * (x @ W1) (first n*64 threads)
__global__ void k_fillx1(const int* __restrict__ src, const int* __restrict__ dst, int E,
                         const float* __restrict__ x, const float* __restrict__ W1, int n) {
    int i = blockIdx.x * blockDim.x + threadIdx.x;
    if (i < E) {
        int d = dst[i];
        int p = atomicAdd(&g_cur[d], 1);
        g_csrc[p] = src[i];
    }
    if (i < n * HH) {
        int node = i >> 6;
        int j = i & 63;
        float v = g_dinv[node] * (x[2 * node] * W1[j] + x[2 * node + 1] * W1[HH + j]);
        g_th[i] = __float2half(v);
    }
}

// warp-per-node aggregation (fp16 gather, fp32 accum): f1 = relu(dinv*(self+sum)+b1)
__global__ void k_agg1(const float* __restrict__ b1, int n) {
    const __half2* t2 = reinterpret_cast<const __half2*>(g_th);
    int w = (blockIdx.x * blockDim.x + threadIdx.x) >> 5;
    int lane = threadIdx.x & 31;
    if (w >= n) return;
    int beg = g_off[w];
    int len = g_ideg[w];
    float2 acc = __half22float2(t2[w * 32 + lane]);   // self
    for (int base = 0; base < len; base += 32) {
        int rem = len - base;
        int m = rem < 32 ? rem : 32;
        int idx = (lane < m) ? g_csrc[beg + base + lane] : 0;
        #pragma unroll 4
        for (int k = 0; k < m; k++) {
            int s = __shfl_sync(0xffffffffu, idx, k);
            float2 v = __half22float2(t2[s * 32 + lane]);
            acc.x += v.x;
            acc.y += v.y;
        }
    }
    float dv = g_dinv[w];
    float2 bb = *reinterpret_cast<const float2*>(&b1[lane * 2]);
    float2 o;
    o.x = fmaxf(fmaf(dv, acc.x, bb.x), 0.0f);
    o.y = fmaxf(fmaf(dv, acc.y, bb.y), 0.0f);
    *reinterpret_cast<float2*>(&g_f[w * HH + lane * 2]) = o;
}

// t2' = dinv * (f1 @ W2); 4 nodes per 256-thread block, W2 in smem; fp16 store
__global__ void k_xform2(const float* __restrict__ W2, int n) {
    __shared__ float sW[HH * HH];
    __shared__ float sRow[4 * HH];
    int tid = threadIdx.x;
    int grp = tid >> 6;
    int j = tid & 63;
    int node = blockIdx.x * 4 + grp;

    for (int i = tid; i < HH * HH; i += 256) sW[i] = W2[i];
    if (node < n) sRow[grp * HH + j] = g_f[node * HH + j];
    __syncthreads();

    if (node >= n) return;
    float acc = 0.0f;
    #pragma unroll
    for (int kk = 0; kk < HH; kk++) acc += sRow[grp * HH + kk] * sW[kk * HH + j];
    g_th[node * HH + j] = __float2half(g_dinv[node] * acc);
}

// warp-per-node layer-2 agg fused with pooling
__global__ void k_agg2pool(const float* __restrict__ b2, const int* __restrict__ batch, int n) {
    const __half2* t2 = reinterpret_cast<const __half2*>(g_th);
    int w = (blockIdx.x * blockDim.x + threadIdx.x) >> 5;
    int lane = threadIdx.x & 31;
    if (w >= n) return;
    int beg = g_off[w];
    int len = g_ideg[w];
    float2 acc = __half22float2(t2[w * 32 + lane]);
    for (int base = 0; base < len; base += 32) {
        int rem = len - base;
        int m = rem < 32 ? rem : 32;
        int idx = (lane < m) ? g_csrc[beg + base + lane] : 0;
        #pragma unroll 4
        for (int k = 0; k < m; k++) {
            int s = __shfl_sync(0xffffffffu, idx, k);
            float2 v = __half22float2(t2[s * 32 + lane]);
            acc.x += v.x;
            acc.y += v.y;
        }
    }
    float dv = g_dinv[w];
    float2 bb = *reinterpret_cast<const float2*>(&b2[lane * 2]);
    float vx = fmaxf(fmaf(dv, acc.x, bb.x), 0.0f);
    float vy = fmaxf(fmaf(dv, acc.y, bb.y), 0.0f);
    int b = batch[w];
    atomicAdd(&g_pool[b * HH + lane * 2 + 0], vx);
    atomicAdd(&g_pool[b * HH + lane * 2 + 1], vy);
}

// Head: g = pool/cnt; a = relu(g@Wf1+bf1); out = a@Wf2+bf2
__global__ void k_final(const float* __restrict__ Wf1, const float* __restrict__ bf1,
                        const float* __restrict__ Wf2, const float* __restrict__ bf2,
                        float* __restrict__ out) {
    __shared__ float sg[HH];
    __shared__ float sa[HH];
    int b = blockIdx.x;
    int j = threadIdx.x;

    float c = fmaxf(g_cnt[b], 1.0f);
    sg[j] = g_pool[b * HH + j] / c;
    __syncthreads();

    float acc = bf1[j];
    #pragma unroll
    for (int k = 0; k < HH; k++) acc += sg[k] * Wf1[k * HH + j];
    sa[j] = fmaxf(acc, 0.0f);
    __syncthreads();

    if (j < 4) {
        float o = bf2[j];
        #pragma unroll
        for (int k = 0; k < HH; k++) o += sa[k] * Wf2[k * 4 + j];
        out[b * 4 + j] = o;
    }
}

extern "C" void kernel_launch(void* const* d_in, const int* in_sizes, int n_in,
                              void* d_out, int out_size) {
    const float* x          = (const float*)d_in[0];
    const int*   edge_index = (const int*)d_in[1];
    const int*   batch      = (const int*)d_in[2];
    int wb = n_in - 8;
    const float* W1  = (const float*)d_in[wb + 0];
    const float* b1  = (const float*)d_in[wb + 1];
    const float* W2  = (const float*)d_in[wb + 2];
    const float* b2  = (const float*)d_in[wb + 3];
    const float* Wf1 = (const float*)d_in[wb + 4];
    const float* bf1 = (const float*)d_in[wb + 5];
    const float* Wf2 = (const float*)d_in[wb + 6];
    const float* bf2 = (const float*)d_in[wb + 7];

    int N = in_sizes[0] / 2;   // 100000
    int E = in_sizes[1] / 2;   // 1200000
    const int* src = edge_index;
    const int* dst = edge_index + E;

    float* out = (float*)d_out;
    (void)out_size;

    const int T = 256;
    int gN  = (N + T - 1) / T;
    int gE  = (E + T - 1) / T;
    int gF  = (N * HH + T - 1) / T;   // covers both fill (E) and xform1 (N*64)
    int gW  = (N * 32 + T - 1) / T;   // warp-per-node (8 nodes / 256-thr block)

    // launch order chosen so ncu -s 5 captures k_agg1
    k_zero_all<<<gN, T>>>();                       // 0
    k_hist<<<gE, T>>>(dst, E);                     // 1
    k_scan1<<<NBLK, SCAN_B>>>();                   // 2
    k_scan23<<<NBLK, SCAN_B>>>(batch, N);          // 3
    k_fillx1<<<gF, T>>>(src, dst, E, x, W1, N);    // 4
    k_agg1<<<gW, T>>>(b1, N);                      // 5  <- profiled
    k_xform2<<<(N + 3) / 4, 256>>>(W2, N);         // 6
    k_agg2pool<<<gW, T>>>(b2, batch, N);           // 7
    k_final<<<GG, HH>>>(Wf1, bf1, Wf2, bf2, out);  // 8
}

// round 7
// speedup vs baseline: 2.0225x; 1.4157x over previous
#include <cuda_runtime.h>
#include <cuda_fp16.h>

#define NN 100000
#define EE_MAX 1300000
#define HH 64
#define GG 512
#define SCAN_B 256
#define NBLK ((NN + SCAN_B - 1) / SCAN_B)   // 391

// -------- scratch (device globals) --------
__device__ int    g_ideg[NN];
__device__ int    g_off[NN];
__device__ int    g_cur[NN];
__device__ int    g_bsum[NBLK];
__device__ int    g_csrc[EE_MAX];
__device__ float  g_dinv[NN];
__device__ __half g_th[NN * HH];      // pre-scaled transformed features (fp16)
__device__ float  g_f[NN * HH];       // layer-1 output (fp32)
__device__ float  g_pool[GG * HH];
__device__ float  g_cnt[GG];

__global__ void k_zero_all() {
    int i = blockIdx.x * blockDim.x + threadIdx.x;
    if (i < NN) g_ideg[i] = 0;
    if (i < GG * HH) g_pool[i] = 0.0f;
    if (i < GG) g_cnt[i] = 0.0f;
}

__global__ void k_hist(const int* __restrict__ dst, int E) {
    int e = blockIdx.x * blockDim.x + threadIdx.x;
    if (e < E) atomicAdd(&g_ideg[dst[e]], 1);
}

// block-local inclusive scan -> exclusive offsets + per-block sums
__global__ void k_scan1() {
    __shared__ int s[SCAN_B];
    int i = blockIdx.x * SCAN_B + threadIdx.x;
    int v = (i < NN) ? g_ideg[i] : 0;
    s[threadIdx.x] = v;
    __syncthreads();
    for (int o = 1; o < SCAN_B; o <<= 1) {
        int t = (threadIdx.x >= o) ? s[threadIdx.x - o] : 0;
        __syncthreads();
        s[threadIdx.x] += t;
        __syncthreads();
    }
    if (i < NN) g_off[i] = s[threadIdx.x] - v;
    if (threadIdx.x == SCAN_B - 1) g_bsum[blockIdx.x] = s[SCAN_B - 1];
}

// fused: per-block prefix over g_bsum + finalize offsets/dinv/cursors + graph counts
// (graph counts via warp-aggregated atomics; batch is sorted so ~1 atomic/warp)
__global__ void k_scan23(const int* __restrict__ batch, int n) {
    __shared__ int red[8];
    __shared__ int ssum;
    int tid = threadIdx.x;
    int partial = 0;
    for (int j = tid; j < (int)blockIdx.x; j += SCAN_B) partial += g_bsum[j];
    #pragma unroll
    for (int o = 16; o; o >>= 1) partial += __shfl_down_sync(0xffffffffu, partial, o);
    if ((tid & 31) == 0) red[tid >> 5] = partial;
    __syncthreads();
    if (tid == 0) {
        int s = 0;
        #pragma unroll
        for (int k = 0; k < 8; k++) s += red[k];
        ssum = s;
    }
    __syncthreads();
    int i = blockIdx.x * SCAN_B + tid;
    if (i < n) {
        int o = g_off[i] + ssum;
        g_off[i] = o;
        g_cur[i] = o;
        g_dinv[i] = rsqrtf((float)g_ideg[i] + 1.0f);
        // warp-aggregated count
        int b = batch[i];
        unsigned active = __activemask();
        unsigned peers = __match_any_sync(active, b);
        int leader = __ffs(peers) - 1;
        int cnt = __popc(peers);
        if ((tid & 31) == leader) atomicAdd(&g_cnt[b], (float)cnt);
    }
}

// fused: CSR fill (first E threads) + layer-1 transform t1' = dinv * (x @ W1)
__global__ void k_fillx1(const int* __restrict__ src, const int* __restrict__ dst, int E,
                         const float* __restrict__ x, const float* __restrict__ W1, int n) {
    int i = blockIdx.x * blockDim.x + threadIdx.x;
    if (i < E) {
        int d = dst[i];
        int p = atomicAdd(&g_cur[d], 1);
        g_csrc[p] = src[i];
    }
    if (i < n * HH) {
        int node = i >> 6;
        int j = i & 63;
        float v = g_dinv[node] * (x[2 * node] * W1[j] + x[2 * node + 1] * W1[HH + j]);
        g_th[i] = __float2half(v);
    }
}

// warp-per-node aggregation (fp16 gather, fp32 accum, 2 edges/step)
__global__ void k_agg1(const float* __restrict__ b1, int n) {
    const __half2* t2 = reinterpret_cast<const __half2*>(g_th);
    int w = (blockIdx.x * blockDim.x + threadIdx.x) >> 5;
    int lane = threadIdx.x & 31;
    if (w >= n) return;
    int beg = g_off[w];
    int len = g_ideg[w];
    float2 acc = __half22float2(t2[w * 32 + lane]);   // self
    float2 acc2 = make_float2(0.0f, 0.0f);
    for (int base = 0; base < len; base += 32) {
        int rem = len - base;
        int m = rem < 32 ? rem : 32;
        int idx = (lane < m) ? g_csrc[beg + base + lane] : 0;
        int k = 0;
        for (; k + 2 <= m; k += 2) {
            int s0 = __shfl_sync(0xffffffffu, idx, k);
            int s1 = __shfl_sync(0xffffffffu, idx, k + 1);
            float2 v0 = __half22float2(t2[s0 * 32 + lane]);
            float2 v1 = __half22float2(t2[s1 * 32 + lane]);
            acc.x += v0.x; acc.y += v0.y;
            acc2.x += v1.x; acc2.y += v1.y;
        }
        if (k < m) {
            int s0 = __shfl_sync(0xffffffffu, idx, k);
            float2 v0 = __half22float2(t2[s0 * 32 + lane]);
            acc.x += v0.x; acc.y += v0.y;
        }
    }
    acc.x += acc2.x; acc.y += acc2.y;
    float dv = g_dinv[w];
    float2 bb = *reinterpret_cast<const float2*>(&b1[lane * 2]);
    float2 o;
    o.x = fmaxf(fmaf(dv, acc.x, bb.x), 0.0f);
    o.y = fmaxf(fmaf(dv, acc.y, bb.y), 0.0f);
    *reinterpret_cast<float2*>(&g_f[w * HH + lane * 2]) = o;
}

// t2' = dinv * (f1 @ W2); 16 nodes per 256-thread block (16 thr/node, 4 outputs each)
__global__ void k_xform2(const float* __restrict__ W2, int n) {
    __shared__ float sW[HH * HH];        // W2[k][j], row-major
    __shared__ float sRow[16][HH + 4];   // padded rows
    int tid = threadIdx.x;
    int nl = tid >> 4;          // node-local 0..15
    int q  = tid & 15;          // 16 threads per node
    int j4 = q * 4;             // 4 consecutive output features
    int node = blockIdx.x * 16 + nl;

    for (int i = tid; i < HH * HH; i += 256) sW[i] = W2[i];
    // load 16 rows of f1: thread loads 4 floats
    if (node < n) {
        float4 r = *reinterpret_cast<const float4*>(&g_f[node * HH + j4]);
        sRow[nl][j4 + 0] = r.x; sRow[nl][j4 + 1] = r.y;
        sRow[nl][j4 + 2] = r.z; sRow[nl][j4 + 3] = r.w;
    }
    __syncthreads();

    if (node >= n) return;
    float a0 = 0.f, a1 = 0.f, a2 = 0.f, a3 = 0.f;
    #pragma unroll
    for (int k = 0; k < HH; k++) {
        float r = sRow[nl][k];
        float4 wv = *reinterpret_cast<const float4*>(&sW[k * HH + j4]);
        a0 = fmaf(r, wv.x, a0);
        a1 = fmaf(r, wv.y, a1);
        a2 = fmaf(r, wv.z, a2);
        a3 = fmaf(r, wv.w, a3);
    }
    float dv = g_dinv[node];
    __half2* out = reinterpret_cast<__half2*>(&g_th[node * HH + j4]);
    out[0] = __floats2half2_rn(dv * a0, dv * a1);
    out[1] = __floats2half2_rn(dv * a2, dv * a3);
}

// warp-per-node layer-2 agg fused with pooling
__global__ void k_agg2pool(const float* __restrict__ b2, const int* __restrict__ batch, int n) {
    const __half2* t2 = reinterpret_cast<const __half2*>(g_th);
    int w = (blockIdx.x * blockDim.x + threadIdx.x) >> 5;
    int lane = threadIdx.x & 31;
    if (w >= n) return;
    int beg = g_off[w];
    int len = g_ideg[w];
    float2 acc = __half22float2(t2[w * 32 + lane]);
    float2 acc2 = make_float2(0.0f, 0.0f);
    for (int base = 0; base < len; base += 32) {
        int rem = len - base;
        int m = rem < 32 ? rem : 32;
        int idx = (lane < m) ? g_csrc[beg + base + lane] : 0;
        int k = 0;
        for (; k + 2 <= m; k += 2) {
            int s0 = __shfl_sync(0xffffffffu, idx, k);
            int s1 = __shfl_sync(0xffffffffu, idx, k + 1);
            float2 v0 = __half22float2(t2[s0 * 32 + lane]);
            float2 v1 = __half22float2(t2[s1 * 32 + lane]);
            acc.x += v0.x; acc.y += v0.y;
            acc2.x += v1.x; acc2.y += v1.y;
        }
        if (k < m) {
            int s0 = __shfl_sync(0xffffffffu, idx, k);
            float2 v0 = __half22float2(t2[s0 * 32 + lane]);
            acc.x += v0.x; acc.y += v0.y;
        }
    }
    acc.x += acc2.x; acc.y += acc2.y;
    float dv = g_dinv[w];
    float2 bb = *reinterpret_cast<const float2*>(&b2[lane * 2]);
    float vx = fmaxf(fmaf(dv, acc.x, bb.x), 0.0f);
    float vy = fmaxf(fmaf(dv, acc.y, bb.y), 0.0f);
    int b = batch[w];
    atomicAdd(&g_pool[b * HH + lane * 2 + 0], vx);
    atomicAdd(&g_pool[b * HH + lane * 2 + 1], vy);
}

// Head: g = pool/cnt; a = relu(g@Wf1+bf1); out = a@Wf2+bf2
__global__ void k_final(const float* __restrict__ Wf1, const float* __restrict__ bf1,
                        const float* __restrict__ Wf2, const float* __restrict__ bf2,
                        float* __restrict__ out) {
    __shared__ float sg[HH];
    __shared__ float sa[HH];
    int b = blockIdx.x;
    int j = threadIdx.x;

    float c = fmaxf(g_cnt[b], 1.0f);
    sg[j] = g_pool[b * HH + j] / c;
    __syncthreads();

    float acc = bf1[j];
    #pragma unroll
    for (int k = 0; k < HH; k++) acc += sg[k] * Wf1[k * HH + j];
    sa[j] = fmaxf(acc, 0.0f);
    __syncthreads();

    if (j < 4) {
        float o = bf2[j];
        #pragma unroll
        for (int k = 0; k < HH; k++) o += sa[k] * Wf2[k * 4 + j];
        out[b * 4 + j] = o;
    }
}

extern "C" void kernel_launch(void* const* d_in, const int* in_sizes, int n_in,
                              void* d_out, int out_size) {
    const float* x          = (const float*)d_in[0];
    const int*   edge_index = (const int*)d_in[1];
    const int*   batch      = (const int*)d_in[2];
    int wb = n_in - 8;
    const float* W1  = (const float*)d_in[wb + 0];
    const float* b1  = (const float*)d_in[wb + 1];
    const float* W2  = (const float*)d_in[wb + 2];
    const float* b2  = (const float*)d_in[wb + 3];
    const float* Wf1 = (const float*)d_in[wb + 4];
    const float* bf1 = (const float*)d_in[wb + 5];
    const float* Wf2 = (const float*)d_in[wb + 6];
    const float* bf2 = (const float*)d_in[wb + 7];

    int N = in_sizes[0] / 2;   // 100000
    int E = in_sizes[1] / 2;   // 1200000
    const int* src = edge_index;
    const int* dst = edge_index + E;

    float* out = (float*)d_out;
    (void)out_size;

    const int T = 256;
    int gN  = (N + T - 1) / T;
    int gE  = (E + T - 1) / T;
    int gF  = (N * HH + T - 1) / T;   // covers both fill (E) and xform1 (N*64)
    int gW  = (N * 32 + T - 1) / T;   // warp-per-node (8 nodes / 256-thr block)

    k_zero_all<<<gN, T>>>();                       // 0
    k_hist<<<gE, T>>>(dst, E);                     // 1
    k_scan1<<<NBLK, SCAN_B>>>();                   // 2
    k_scan23<<<NBLK, SCAN_B>>>(batch, N);          // 3  <- profiled (verify atomic fix)
    k_fillx1<<<gF, T>>>(src, dst, E, x, W1, N);    // 4
    k_agg1<<<gW, T>>>(b1, N);                      // 5
    k_xform2<<<(N + 15) / 16, 256>>>(W2, N);       // 6
    k_agg2pool<<<gW, T>>>(b2, batch, N);           // 7
    k_final<<<GG, HH>>>(Wf1, bf1, Wf2, bf2, out);  // 8
}